// round 1
// baseline (speedup 1.0000x reference)
#include <cuda_runtime.h>
#include <math.h>

// router: per-token top2-softmax + soft-softmax blended 4-way combine.
// N = 32768 tokens, D = 512, K = 4. Single-pass: x kept in registers.

#define THREADS 128
#define WARPS_PER_BLOCK 4
#define D_DIM 512
#define SMEM_FLOATS 16384  // W_top (4x2048) + W_soft (4x2048)

__device__ __forceinline__ void compute_w(const float lt_in[4], const float ls_in[4],
                                          const float bt[4], const float bs[4],
                                          float a, float w[4]) {
    float t[4], s[4];
#pragma unroll
    for (int k = 0; k < 4; k++) { t[k] = lt_in[k] + bt[k]; s[k] = ls_in[k] + bs[k]; }

    // soft = softmax(s)
    float mx = fmaxf(fmaxf(s[0], s[1]), fmaxf(s[2], s[3]));
    float e[4], sum = 0.f;
#pragma unroll
    for (int k = 0; k < 4; k++) { e[k] = expf(s[k] - mx); sum += e[k]; }
    float inv = 1.f / sum;

    // top-2 of t (first occurrence on ties, matching jax top_k)
    int i1 = 0; float v1 = t[0];
#pragma unroll
    for (int k = 1; k < 4; k++) { if (t[k] > v1) { v1 = t[k]; i1 = k; } }
    int i2 = -1; float v2 = -3.402823466e38f;
#pragma unroll
    for (int k = 0; k < 4; k++) { if (k != i1 && t[k] > v2) { v2 = t[k]; i2 = k; } }

    float e2 = expf(v2 - v1);          // v2 <= v1, e2 in (0,1]
    float d  = 1.f / (1.f + e2);
    float p1 = d;
    float p2 = e2 * d;

#pragma unroll
    for (int k = 0; k < 4; k++) {
        float hard = (k == i1) ? p1 : ((k == i2) ? p2 : 0.f);
        w[k] = a * hard + (1.f - a) * e[k] * inv;
    }
}

__global__ void __launch_bounds__(THREADS, 2)
router_kernel(const float* __restrict__ m0, const float* __restrict__ m1,
              const float* __restrict__ m2, const float* __restrict__ m3,
              const float* __restrict__ Wt, const float* __restrict__ bt,
              const float* __restrict__ Ws, const float* __restrict__ bs,
              const float* __restrict__ alpha,
              float* __restrict__ out, int n_tokens)
{
    extern __shared__ float sW[];   // [0:8192) = W_top rows, [8192:16384) = W_soft rows

    // Stage W into shared (vectorized, once per block)
    {
        const float4* gt = (const float4*)Wt;
        const float4* gs = (const float4*)Ws;
        float4* st = (float4*)sW;
        float4* ss = (float4*)(sW + 8192);
#pragma unroll 4
        for (int i = threadIdx.x; i < 2048; i += THREADS) {
            st[i] = gt[i];
            ss[i] = gs[i];
        }
    }
    __syncthreads();

    const int lane = threadIdx.x & 31;
    const int warp = threadIdx.x >> 5;
    const int warps_total = gridDim.x * WARPS_PER_BLOCK;
    const int n_pairs = n_tokens >> 1;

    const float a = 1.f / (1.f + expf(-alpha[0]));
    float bt_r[4], bs_r[4];
#pragma unroll
    for (int k = 0; k < 4; k++) { bt_r[k] = __ldg(bt + k); bs_r[k] = __ldg(bs + k); }

    for (int pair = blockIdx.x * WARPS_PER_BLOCK + warp; pair < n_pairs; pair += warps_total) {
        const int base0 = (pair * 2) * D_DIM + lane;  // fits in int (max ~16.7M)
        const int base1 = base0 + D_DIM;

        // ---- Load x for both tokens into registers (coalesced LDG.32) ----
        float xa[4][16], xb[4][16];
#pragma unroll
        for (int m = 0; m < 16; m++) {
            const int o0 = base0 + 32 * m;
            xa[0][m] = __ldg(m0 + o0); xa[1][m] = __ldg(m1 + o0);
            xa[2][m] = __ldg(m2 + o0); xa[3][m] = __ldg(m3 + o0);
        }
#pragma unroll
        for (int m = 0; m < 16; m++) {
            const int o1 = base1 + 32 * m;
            xb[0][m] = __ldg(m0 + o1); xb[1][m] = __ldg(m1 + o1);
            xb[2][m] = __ldg(m2 + o1); xb[3][m] = __ldg(m3 + o1);
        }

        // ---- Partial dot products: 8 rows x 2 tokens ----
        float at0[4] = {0,0,0,0}, as0[4] = {0,0,0,0};
        float at1[4] = {0,0,0,0}, as1[4] = {0,0,0,0};
#pragma unroll
        for (int m = 0; m < 16; m++) {
            const int jb = (lane + 32 * m) * 4;  // element index into a 2048-wide row
            const float A0 = xa[0][m], A1 = xa[1][m], A2 = xa[2][m], A3 = xa[3][m];
            const float B0 = xb[0][m], B1 = xb[1][m], B2 = xb[2][m], B3 = xb[3][m];
#pragma unroll
            for (int r = 0; r < 4; r++) {
                const float4 wt = *(const float4*)&sW[r * 2048 + jb];
                at0[r] += A0 * wt.x + A1 * wt.y + A2 * wt.z + A3 * wt.w;
                at1[r] += B0 * wt.x + B1 * wt.y + B2 * wt.z + B3 * wt.w;
                const float4 ws = *(const float4*)&sW[8192 + r * 2048 + jb];
                as0[r] += A0 * ws.x + A1 * ws.y + A2 * ws.z + A3 * ws.w;
                as1[r] += B0 * ws.x + B1 * ws.y + B2 * ws.z + B3 * ws.w;
            }
        }

        // ---- Butterfly reduction across 32 lanes (all lanes end with full sums) ----
#pragma unroll
        for (int off = 16; off > 0; off >>= 1) {
#pragma unroll
            for (int r = 0; r < 4; r++) {
                at0[r] += __shfl_xor_sync(0xffffffffu, at0[r], off);
                as0[r] += __shfl_xor_sync(0xffffffffu, as0[r], off);
                at1[r] += __shfl_xor_sync(0xffffffffu, at1[r], off);
                as1[r] += __shfl_xor_sync(0xffffffffu, as1[r], off);
            }
        }

        // ---- Routing weights (computed redundantly per lane; cheap) ----
        float w0[4], w1[4];
        compute_w(at0, as0, bt_r, bs_r, a, w0);
        compute_w(at1, as1, bt_r, bs_r, a, w1);

        // ---- Combine + coalesced store ----
#pragma unroll
        for (int m = 0; m < 16; m++) {
            out[base0 + 32 * m] =
                xa[0][m] * w0[0] + xa[1][m] * w0[1] + xa[2][m] * w0[2] + xa[3][m] * w0[3];
        }
#pragma unroll
        for (int m = 0; m < 16; m++) {
            out[base1 + 32 * m] =
                xb[0][m] * w1[0] + xb[1][m] * w1[1] + xb[2][m] * w1[2] + xb[3][m] * w1[3];
        }
    }
}

extern "C" void kernel_launch(void* const* d_in, const int* in_sizes, int n_in,
                              void* d_out, int out_size) {
    const float* m0    = (const float*)d_in[0];
    const float* m1    = (const float*)d_in[1];
    const float* m2    = (const float*)d_in[2];
    const float* m3    = (const float*)d_in[3];
    const float* Wt    = (const float*)d_in[4];
    const float* bt    = (const float*)d_in[5];
    const float* Ws    = (const float*)d_in[6];
    const float* bs    = (const float*)d_in[7];
    const float* alpha = (const float*)d_in[8];
    float* out = (float*)d_out;

    const int n_tokens = in_sizes[0] / D_DIM;  // 32768

    cudaFuncSetAttribute(router_kernel,
                         cudaFuncAttributeMaxDynamicSharedMemorySize,
                         SMEM_FLOATS * (int)sizeof(float));

    int blocks = 2 * 148;  // 2 CTAs/SM, grid-stride over token pairs
    const int n_pairs = n_tokens >> 1;
    if (blocks * WARPS_PER_BLOCK > n_pairs) blocks = (n_pairs + WARPS_PER_BLOCK - 1) / WARPS_PER_BLOCK;

    router_kernel<<<blocks, THREADS, SMEM_FLOATS * sizeof(float)>>>(
        m0, m1, m2, m3, Wt, bt, Ws, bs, alpha, out, n_tokens);
}